// round 2
// baseline (speedup 1.0000x reference)
#include <cuda_runtime.h>
#include <cstdint>

// ---------------- problem constants ----------------
#define N_BATCH 4096
#define PPOINTS 512
#define F0      1023      // layer-0 input features
#define FP0     1024      // padded
#define E       2048      // hidden width
#define OUTW    512
#define K0      (FP0 * 9)   // 9216
#define K1      (E * 9)     // 18432

// ---------------- scratch (static device, allowed) ----------------
__device__ float g_XA[K1 * N_BATCH];   // augmented activations, K-major [K][N]  (302 MB, reused per layer)
__device__ float g_W [K1 * E];         // augmented weights,     K-major [K][O]  (151 MB, reused per layer)
__device__ float g_Y1[N_BATCH * E];    // layer outputs, row-major [N][O]
__device__ float g_Y2[N_BATCH * E];

// ---------------- B-spline (matches reference Cox-de Boor exactly) ----------------
__device__ __forceinline__ float gv(int i) { return (float)(i - 3) * 0.4f - 1.0f; }

__device__ __forceinline__ void bspline8(float x, float* out) {
    float b[11];
#pragma unroll
    for (int j = 0; j < 11; j++)
        b[j] = (x >= gv(j) && x < gv(j + 1)) ? 1.0f : 0.0f;
#pragma unroll
    for (int k = 1; k <= 3; k++) {
#pragma unroll
        for (int j = 0; j <= 10 - k; j++) {
            float la = (x - gv(j))         * (1.0f / (gv(j + k)     - gv(j)));
            float rb = (gv(j + k + 1) - x) * (1.0f / (gv(j + k + 1) - gv(j + 1)));
            b[j] = la * b[j] + rb * b[j + 1];
        }
    }
#pragma unroll
    for (int j = 0; j < 8; j++) out[j] = b[j];
}

// ---------------- expansion kernels ----------------
// Layer 0: features interleave xs/ys. f even -> xs[n][f/2], f odd -> ys[n][f/2], f==1022 -> xs[n][511].
__global__ void expand0_kernel(const float* __restrict__ xs, const float* __restrict__ ys,
                               float* __restrict__ XA) {
    int n = blockIdx.x * blockDim.x + threadIdx.x;   // batch index (coalesced writes)
    int f = blockIdx.y;                              // 0..FP0-1
    float vals[9];
    if (f < F0) {
        int p = f >> 1;
        float x = (f & 1) ? ys[n * PPOINTS + p] : xs[n * PPOINTS + p];
        vals[0] = fmaxf(x, 0.0f);
        bspline8(x, vals + 1);
    } else {
#pragma unroll
        for (int j = 0; j < 9; j++) vals[j] = 0.0f;
    }
    int base = f * 9 * N_BATCH + n;
#pragma unroll
    for (int j = 0; j < 9; j++) XA[base + j * N_BATCH] = vals[j];
}

// Layers 1,2: X is [N][F] row-major (previous layer output), F == padded.
__global__ void expand_kernel(const float* __restrict__ X, float* __restrict__ XA, int F) {
    int n = blockIdx.x * blockDim.x + threadIdx.x;
    int f = blockIdx.y;
    float x = X[n * F + f];
    float vals[9];
    vals[0] = fmaxf(x, 0.0f);
    bspline8(x, vals + 1);
    int base = f * 9 * N_BATCH + n;
#pragma unroll
    for (int j = 0; j < 9; j++) XA[base + j * N_BATCH] = vals[j];
}

// ---------------- weight build: W[k=f*9+j][o], scaler folded in ----------------
__global__ void build_w_kernel(const float* __restrict__ bw, const float* __restrict__ sw,
                               const float* __restrict__ sc, float* __restrict__ W,
                               int O, int F) {
    int o = blockIdx.x * blockDim.x + threadIdx.x;   // coalesced writes
    int f = blockIdx.y;                              // 0..Fp-1
    float vals[9];
    if (f < F) {
        size_t idx = (size_t)o * F + f;
        float s = sc[idx];
        vals[0] = bw[idx];
        const float4* sp = reinterpret_cast<const float4*>(sw + idx * 8);
        float4 s0 = sp[0], s1 = sp[1];
        vals[1] = s0.x * s; vals[2] = s0.y * s; vals[3] = s0.z * s; vals[4] = s0.w * s;
        vals[5] = s1.x * s; vals[6] = s1.y * s; vals[7] = s1.z * s; vals[8] = s1.w * s;
    } else {
#pragma unroll
        for (int j = 0; j < 9; j++) vals[j] = 0.0f;
    }
    size_t base = (size_t)f * 9 * O + o;
#pragma unroll
    for (int j = 0; j < 9; j++) W[base + (size_t)j * O] = vals[j];
}

// ---------------- packed f32x2 helpers (full-rate fp32 path on sm_103a) ----------------
__device__ __forceinline__ unsigned long long ffma2(unsigned long long a, unsigned long long b,
                                                    unsigned long long c) {
    unsigned long long d;
    asm("fma.rn.f32x2 %0, %1, %2, %3;" : "=l"(d) : "l"(a), "l"(b), "l"(c));
    return d;
}
__device__ __forceinline__ unsigned long long pack2(float v) {
    unsigned long long d;
    asm("mov.b64 %0, {%1, %1};" : "=l"(d) : "f"(v));
    return d;
}
__device__ __forceinline__ float2 u2f(unsigned long long u) {
    float2 r;
    asm("mov.b64 {%0, %1}, %2;" : "=f"(r.x), "=f"(r.y) : "l"(u));
    return r;
}

// ---------------- GEMM: C[n][o] = sum_k A[k][n] * B[k][o] ----------------
#define BM 128
#define BN 128
#define BK 16

__global__ void __launch_bounds__(256, 2)
gemm_kernel(const float* __restrict__ A,   // [K][N]
            const float* __restrict__ B,   // [K][O]
            float* __restrict__ C,         // [N][O]
            int N, int O, int K) {
    __shared__ float As[2][BK][BM];
    __shared__ float Bs[2][BK][BN];

    int tid = threadIdx.x;
    int bn = blockIdx.x * BM;
    int bo = blockIdx.y * BN;

    int lk = tid >> 5;            // 0..7 (rows 0-7 and 8-15)
    int lc = (tid & 31) * 4;      // 0..124

    const float* Aptr = A + bn;
    const float* Bptr = B + bo;

    // initial tile
    float4 pa0 = *(const float4*)&Aptr[(lk)     * N + lc];
    float4 pa1 = *(const float4*)&Aptr[(lk + 8) * N + lc];
    float4 pb0 = *(const float4*)&Bptr[(lk)     * O + lc];
    float4 pb1 = *(const float4*)&Bptr[(lk + 8) * O + lc];
    *(float4*)&As[0][lk][lc]     = pa0;
    *(float4*)&As[0][lk + 8][lc] = pa1;
    *(float4*)&Bs[0][lk][lc]     = pb0;
    *(float4*)&Bs[0][lk + 8][lc] = pb1;
    __syncthreads();

    int ty = tid >> 4, tx = tid & 15;
    int m0 = ty * 8, n0 = tx * 8;

    unsigned long long acc[8][4];
#pragma unroll
    for (int m = 0; m < 8; m++)
#pragma unroll
        for (int p = 0; p < 4; p++) acc[m][p] = 0ULL;

    int cur = 0;
    for (int kt = 0; kt < K; kt += BK) {
        bool has_next = (kt + BK) < K;
        if (has_next) {
            int kn = kt + BK;
            pa0 = *(const float4*)&Aptr[(kn + lk)     * N + lc];
            pa1 = *(const float4*)&Aptr[(kn + lk + 8) * N + lc];
            pb0 = *(const float4*)&Bptr[(kn + lk)     * O + lc];
            pb1 = *(const float4*)&Bptr[(kn + lk + 8) * O + lc];
        }
#pragma unroll
        for (int k = 0; k < BK; k++) {
            float a[8];
            *(float4*)&a[0] = *(const float4*)&As[cur][k][m0];
            *(float4*)&a[4] = *(const float4*)&As[cur][k][m0 + 4];
            ulonglong2 bb01 = *(const ulonglong2*)&Bs[cur][k][n0];
            ulonglong2 bb23 = *(const ulonglong2*)&Bs[cur][k][n0 + 4];
#pragma unroll
            for (int m = 0; m < 8; m++) {
                unsigned long long a2 = pack2(a[m]);
                acc[m][0] = ffma2(a2, bb01.x, acc[m][0]);
                acc[m][1] = ffma2(a2, bb01.y, acc[m][1]);
                acc[m][2] = ffma2(a2, bb23.x, acc[m][2]);
                acc[m][3] = ffma2(a2, bb23.y, acc[m][3]);
            }
        }
        if (has_next) {
            int nb = cur ^ 1;
            *(float4*)&As[nb][lk][lc]     = pa0;
            *(float4*)&As[nb][lk + 8][lc] = pa1;
            *(float4*)&Bs[nb][lk][lc]     = pb0;
            *(float4*)&Bs[nb][lk + 8][lc] = pb1;
            __syncthreads();
        }
        cur ^= 1;
    }

#pragma unroll
    for (int m = 0; m < 8; m++) {
        float2 r0 = u2f(acc[m][0]);
        float2 r1 = u2f(acc[m][1]);
        float2 r2 = u2f(acc[m][2]);
        float2 r3 = u2f(acc[m][3]);
        float4 o0 = make_float4(r0.x, r0.y, r1.x, r1.y);
        float4 o1 = make_float4(r2.x, r2.y, r3.x, r3.y);
        float* crow = C + (size_t)(bn + m0 + m) * O + bo + n0;
        *(float4*)&crow[0] = o0;
        *(float4*)&crow[4] = o1;
    }
}

// ---------------- launch ----------------
extern "C" void kernel_launch(void* const* d_in, const int* in_sizes, int n_in,
                              void* d_out, int out_size) {
    const float* xs  = (const float*)d_in[0];
    const float* ys  = (const float*)d_in[1];
    const float* bw0 = (const float*)d_in[2];
    const float* sw0 = (const float*)d_in[3];
    const float* sc0 = (const float*)d_in[4];
    const float* bw1 = (const float*)d_in[5];
    const float* sw1 = (const float*)d_in[6];
    const float* sc1 = (const float*)d_in[7];
    const float* bw2 = (const float*)d_in[8];
    const float* sw2 = (const float*)d_in[9];
    const float* sc2 = (const float*)d_in[10];
    float* out = (float*)d_out;

    float *XA, *W, *Y1, *Y2;
    cudaGetSymbolAddress((void**)&XA, g_XA);
    cudaGetSymbolAddress((void**)&W,  g_W);
    cudaGetSymbolAddress((void**)&Y1, g_Y1);
    cudaGetSymbolAddress((void**)&Y2, g_Y2);

    // ---- layer 0 ----
    expand0_kernel<<<dim3(N_BATCH / 256, FP0), 256>>>(xs, ys, XA);
    build_w_kernel<<<dim3(E / 256, FP0), 256>>>(bw0, sw0, sc0, W, E, F0);
    gemm_kernel<<<dim3(N_BATCH / BM, E / BN), 256>>>(XA, W, Y1, N_BATCH, E, K0);

    // ---- layer 1 ----
    expand_kernel<<<dim3(N_BATCH / 256, E), 256>>>(Y1, XA, E);
    build_w_kernel<<<dim3(E / 256, E), 256>>>(bw1, sw1, sc1, W, E, E);
    gemm_kernel<<<dim3(N_BATCH / BM, E / BN), 256>>>(XA, W, Y2, N_BATCH, E, K1);

    // ---- layer 2 ----
    expand_kernel<<<dim3(N_BATCH / 256, E), 256>>>(Y2, XA, E);
    build_w_kernel<<<dim3(OUTW / 256, E), 256>>>(bw2, sw2, sc2, W, OUTW, E);
    gemm_kernel<<<dim3(N_BATCH / BM, OUTW / BN), 256>>>(XA, W, out, N_BATCH, OUTW, K1);
}

// round 8
// speedup vs baseline: 1.9750x; 1.9750x over previous
#include <cuda_runtime.h>
#include <cuda_bf16.h>
#include <cstdint>

// ---------------- problem constants ----------------
#define N_BATCH 4096
#define PPOINTS 512
#define F0      1023
#define FP0     1024
#define E       2048
#define OUTW    512
#define K0      (FP0 * 9)   // 9216
#define K1      (E * 9)     // 18432
#define CH0     (K0 / 64)   // 144
#define CH1     (K1 / 64)   // 288
#define MT      (N_BATCH / 128) // 32
#define TILE_B  16384           // 128 rows * 64 bf16 * 2B

// ---------------- scratch ----------------
__device__ float g_XA[(size_t)K1 * N_BATCH];  // fp32 K-major (R1 layout)
__device__ float g_W [(size_t)K1 * E];
__device__ float g_Y1[(size_t)N_BATCH * E];
__device__ float g_Y2[(size_t)N_BATCH * E];
__device__ __align__(1024) __nv_bfloat16 g_XAh[(size_t)MT * CH1 * 8192];
__device__ __align__(1024) __nv_bfloat16 g_XAl[(size_t)MT * CH1 * 8192];
__device__ __align__(1024) __nv_bfloat16 g_Wh [(size_t)(E / 128) * CH1 * 8192];
__device__ __align__(1024) __nv_bfloat16 g_Wl [(size_t)(E / 128) * CH1 * 8192];

// ---------------- PTX helpers ----------------
__device__ __forceinline__ uint32_t smem_u32(const void* p) {
    uint32_t a;
    asm("{ .reg .u64 t; cvta.to.shared.u64 t, %1; cvt.u32.u64 %0, t; }" : "=r"(a) : "l"(p));
    return a;
}
__device__ __forceinline__ void cp16(uint32_t dst, const void* src) {
    asm volatile("cp.async.cg.shared.global [%0], [%1], 16;" :: "r"(dst), "l"(src) : "memory");
}
#define CP_COMMIT() asm volatile("cp.async.commit_group;" ::: "memory")
#define CP_WAIT1()  asm volatile("cp.async.wait_group 1;" ::: "memory")
#define CP_WAIT0()  asm volatile("cp.async.wait_group 0;" ::: "memory")

__device__ __forceinline__ uint32_t lds32(uint32_t addr) {
    uint32_t v;
    asm volatile("ld.shared.b32 %0, [%1];" : "=r"(v) : "r"(addr));
    return v;
}
__device__ __forceinline__ void mma16816(float* d, const uint32_t* a, uint32_t b0, uint32_t b1) {
    asm volatile("mma.sync.aligned.m16n8k16.row.col.f32.bf16.bf16.f32 "
        "{%0,%1,%2,%3}, {%4,%5,%6,%7}, {%8,%9}, {%0,%1,%2,%3};"
        : "+f"(d[0]), "+f"(d[1]), "+f"(d[2]), "+f"(d[3])
        : "r"(a[0]), "r"(a[1]), "r"(a[2]), "r"(a[3]), "r"(b0), "r"(b1));
}

// ---------------- B-spline (R1, proven) ----------------
__device__ __forceinline__ float gv(int i) { return (float)(i - 3) * 0.4f - 1.0f; }

__device__ __forceinline__ void bspline8(float x, float* out) {
    float b[11];
#pragma unroll
    for (int j = 0; j < 11; j++)
        b[j] = (x >= gv(j) && x < gv(j + 1)) ? 1.0f : 0.0f;
#pragma unroll
    for (int k = 1; k <= 3; k++) {
#pragma unroll
        for (int j = 0; j <= 10 - k; j++) {
            float la = (x - gv(j))         * (1.0f / (gv(j + k)     - gv(j)));
            float rb = (gv(j + k + 1) - x) * (1.0f / (gv(j + k + 1) - gv(j + 1)));
            b[j] = la * b[j] + rb * b[j + 1];
        }
    }
#pragma unroll
    for (int j = 0; j < 8; j++) out[j] = b[j];
}

// ---------------- R1 producer kernels (verbatim, proven) ----------------
__global__ void expand0_kernel(const float* __restrict__ xs, const float* __restrict__ ys,
                               float* __restrict__ XA) {
    int n = blockIdx.x * blockDim.x + threadIdx.x;
    int f = blockIdx.y;
    float vals[9];
    if (f < F0) {
        int p = f >> 1;
        float x = (f & 1) ? ys[n * PPOINTS + p] : xs[n * PPOINTS + p];
        vals[0] = fmaxf(x, 0.0f);
        bspline8(x, vals + 1);
    } else {
#pragma unroll
        for (int j = 0; j < 9; j++) vals[j] = 0.0f;
    }
    int base = f * 9 * N_BATCH + n;
#pragma unroll
    for (int j = 0; j < 9; j++) XA[base + j * N_BATCH] = vals[j];
}

__global__ void expand_kernel(const float* __restrict__ X, float* __restrict__ XA, int F) {
    int n = blockIdx.x * blockDim.x + threadIdx.x;
    int f = blockIdx.y;
    float x = X[n * F + f];
    float vals[9];
    vals[0] = fmaxf(x, 0.0f);
    bspline8(x, vals + 1);
    int base = f * 9 * N_BATCH + n;
#pragma unroll
    for (int j = 0; j < 9; j++) XA[base + j * N_BATCH] = vals[j];
}

__global__ void build_w_kernel(const float* __restrict__ bw, const float* __restrict__ sw,
                               const float* __restrict__ sc, float* __restrict__ W,
                               int O, int F) {
    int o = blockIdx.x * blockDim.x + threadIdx.x;
    int f = blockIdx.y;
    float vals[9];
    if (f < F) {
        size_t idx = (size_t)o * F + f;
        float s = sc[idx];
        vals[0] = bw[idx];
        const float4* sp = reinterpret_cast<const float4*>(sw + idx * 8);
        float4 s0 = sp[0], s1 = sp[1];
        vals[1] = s0.x * s; vals[2] = s0.y * s; vals[3] = s0.z * s; vals[4] = s0.w * s;
        vals[5] = s1.x * s; vals[6] = s1.y * s; vals[7] = s1.z * s; vals[8] = s1.w * s;
    } else {
#pragma unroll
        for (int j = 0; j < 9; j++) vals[j] = 0.0f;
    }
    size_t base = (size_t)f * 9 * O + o;
#pragma unroll
    for (int j = 0; j < 9; j++) W[base + (size_t)j * O] = vals[j];
}

// ---------------- convert: fp32 K-major -> bf16 hi/lo tiles ----------------
// S[K][Ncols] -> tile (rt*NCH + c): [128 rows][64 cols bf16], row = col-index of S,
// col = k - c*64. Pure transform, no math.
__device__ __forceinline__ void split_store(float v0, float v1, uint32_t& hw, uint32_t& lw) {
    __nv_bfloat16 h0 = __float2bfloat16_rn(v0);
    __nv_bfloat16 h1 = __float2bfloat16_rn(v1);
    __nv_bfloat16 l0 = __float2bfloat16_rn(v0 - __bfloat162float(h0));
    __nv_bfloat16 l1 = __float2bfloat16_rn(v1 - __bfloat162float(h1));
    hw = (uint32_t)__bfloat16_as_ushort(h0) | ((uint32_t)__bfloat16_as_ushort(h1) << 16);
    lw = (uint32_t)__bfloat16_as_ushort(l0) | ((uint32_t)__bfloat16_as_ushort(l1) << 16);
}

__global__ void conv_tiles(const float* __restrict__ S, __nv_bfloat16* __restrict__ Th,
                           __nv_bfloat16* __restrict__ Tl, int Ncols, int NCH) {
    int c = blockIdx.x;             // k-chunk
    int rt = blockIdx.y;            // 128-row tile
    int tid = threadIdx.x;          // 256
    int row = tid & 127;
    int half = tid >> 7;            // cols 0-31 / 32-63
    int n = rt * 128 + row;
    const float* src = S + (size_t)(c * 64 + half * 32) * Ncols + n;
    size_t tb = ((size_t)(rt * NCH + c)) * TILE_B + (size_t)row * 128 + half * 64;
    char* ph = (char*)Th + tb;
    char* pl = (char*)Tl + tb;
#pragma unroll
    for (int g = 0; g < 4; g++) {
        uint32_t hw[4], lw[4];
#pragma unroll
        for (int e = 0; e < 8; e += 2) {
            float v0 = src[(size_t)(g * 8 + e) * Ncols];
            float v1 = src[(size_t)(g * 8 + e + 1) * Ncols];
            split_store(v0, v1, hw[e >> 1], lw[e >> 1]);
        }
        *(uint4*)(ph + g * 16) = make_uint4(hw[0], hw[1], hw[2], hw[3]);
        *(uint4*)(pl + g * 16) = make_uint4(lw[0], lw[1], lw[2], lw[3]);
    }
}

// ---------------- HMMA GEMM: CTA 128m x 256n, 8 warps of 64x64 (R6) ----------------
#define SROW    144
#define A_HOFF  0
#define A_LOFF  18432
#define B_HOFF  36864
#define B_LOFF  73728
#define STAGE_B 110592
#define DSMEM   (2 * STAGE_B)

__global__ void __launch_bounds__(256, 1)
gemm_hmma(const __nv_bfloat16* __restrict__ Ah, const __nv_bfloat16* __restrict__ Al,
          const __nv_bfloat16* __restrict__ Bh, const __nv_bfloat16* __restrict__ Bl,
          float* __restrict__ C, int O, int NCH) {
    extern __shared__ __align__(1024) char dynsmem[];
    uint32_t sb = smem_u32(dynsmem);
    int tid = threadIdx.x;
    int bo = blockIdx.x, bm = blockIdx.y;
    int w = tid >> 5, lane = tid & 31;
    int wm = (w & 1) * 64;
    int wn = (w >> 1) * 64;

    const char* pAh = (const char*)Ah + (size_t)bm * NCH * TILE_B;
    const char* pAl = (const char*)Al + (size_t)bm * NCH * TILE_B;
    const char* pB0h = (const char*)Bh + (size_t)(2 * bo) * NCH * TILE_B;
    const char* pB0l = (const char*)Bl + (size_t)(2 * bo) * NCH * TILE_B;
    const char* pB1h = (const char*)Bh + (size_t)(2 * bo + 1) * NCH * TILE_B;
    const char* pB1l = (const char*)Bl + (size_t)(2 * bo + 1) * NCH * TILE_B;

#define LOADC(cc, stg) do { \
        size_t go_ = (size_t)(cc) * TILE_B; \
        uint32_t d_ = sb + (stg) * STAGE_B; \
        _Pragma("unroll") \
        for (int r_ = 0; r_ < 4; r_++) { \
            uint32_t q_ = (uint32_t)(r_ * 256 + tid); \
            uint32_t ds_ = (q_ >> 3) * SROW + (q_ & 7) * 16; \
            cp16(d_ + A_HOFF + ds_, pAh + go_ + q_ * 16); \
            cp16(d_ + A_LOFF + ds_, pAl + go_ + q_ * 16); \
            cp16(d_ + B_HOFF + ds_, pB0h + go_ + q_ * 16); \
            cp16(d_ + B_LOFF + ds_, pB0l + go_ + q_ * 16); \
            uint32_t ds2_ = ds_ + 128 * SROW; \
            cp16(d_ + B_HOFF + ds2_, pB1h + go_ + q_ * 16); \
            cp16(d_ + B_LOFF + ds2_, pB1l + go_ + q_ * 16); \
        } \
        CP_COMMIT(); \
    } while (0)

    float acc[4][8][4];
#pragma unroll
    for (int mi = 0; mi < 4; mi++)
#pragma unroll
        for (int ni = 0; ni < 8; ni++)
#pragma unroll
            for (int q = 0; q < 4; q++) acc[mi][ni][q] = 0.0f;

    LOADC(0, 0);

    uint32_t afr = (uint32_t)(wm + (lane >> 2)) * SROW + (uint32_t)(lane & 3) * 4;
    uint32_t bfr = (uint32_t)(wn + (lane >> 2)) * SROW + (uint32_t)(lane & 3) * 4;

    for (int c = 0; c < NCH; c++) {
        if (c + 1 < NCH) { LOADC(c + 1, (c + 1) & 1); CP_WAIT1(); }
        else             { CP_WAIT0(); }
        __syncthreads();

        uint32_t S = sb + (c & 1) * STAGE_B;
        uint32_t aB = S + A_HOFF + afr;
        uint32_t bB = S + B_HOFF + bfr;

#pragma unroll
        for (int ks = 0; ks < 4; ks++) {
            uint32_t ko = (uint32_t)ks * 32;
            uint32_t bh[8][2], bl[8][2];
#pragma unroll
            for (int ni = 0; ni < 8; ni++) {
                uint32_t ad = bB + (uint32_t)ni * (8 * SROW) + ko;
                bh[ni][0] = lds32(ad);
                bh[ni][1] = lds32(ad + 16);
                bl[ni][0] = lds32(ad + (B_LOFF - B_HOFF));
                bl[ni][1] = lds32(ad + (B_LOFF - B_HOFF) + 16);
            }
#pragma unroll
            for (int mi = 0; mi < 4; mi++) {
                uint32_t aa = aB + (uint32_t)mi * (16 * SROW) + ko;
                uint32_t ah4[4], al4[4];
                ah4[0] = lds32(aa);
                ah4[1] = lds32(aa + 8 * SROW);
                ah4[2] = lds32(aa + 16);
                ah4[3] = lds32(aa + 8 * SROW + 16);
                al4[0] = lds32(aa + A_LOFF);
                al4[1] = lds32(aa + A_LOFF + 8 * SROW);
                al4[2] = lds32(aa + A_LOFF + 16);
                al4[3] = lds32(aa + A_LOFF + 8 * SROW + 16);
#pragma unroll
                for (int ni = 0; ni < 8; ni++) {
                    mma16816(acc[mi][ni], ah4, bh[ni][0], bh[ni][1]);
                    mma16816(acc[mi][ni], ah4, bl[ni][0], bl[ni][1]);
                    mma16816(acc[mi][ni], al4, bh[ni][0], bh[ni][1]);
                }
            }
        }
        __syncthreads();
    }

    int er = lane >> 2, ec = (lane & 3) * 2;
#pragma unroll
    for (int mi = 0; mi < 4; mi++)
#pragma unroll
        for (int ni = 0; ni < 8; ni++) {
            size_t row0 = (size_t)(bm * 128 + wm + mi * 16 + er);
            size_t col  = (size_t)(bo * 256 + wn + ni * 8 + ec);
            *(float2*)(C + row0 * O + col)       = make_float2(acc[mi][ni][0], acc[mi][ni][1]);
            *(float2*)(C + (row0 + 8) * O + col) = make_float2(acc[mi][ni][2], acc[mi][ni][3]);
        }
#undef LOADC
}

// ---------------- launch ----------------
extern "C" void kernel_launch(void* const* d_in, const int* in_sizes, int n_in,
                              void* d_out, int out_size) {
    const float* xs  = (const float*)d_in[0];
    const float* ys  = (const float*)d_in[1];
    const float* bw0 = (const float*)d_in[2];
    const float* sw0 = (const float*)d_in[3];
    const float* sc0 = (const float*)d_in[4];
    const float* bw1 = (const float*)d_in[5];
    const float* sw1 = (const float*)d_in[6];
    const float* sc1 = (const float*)d_in[7];
    const float* bw2 = (const float*)d_in[8];
    const float* sw2 = (const float*)d_in[9];
    const float* sc2 = (const float*)d_in[10];
    float* out = (float*)d_out;

    float *XA, *W, *Y1, *Y2;
    __nv_bfloat16 *XAh, *XAl, *Wh, *Wl;
    cudaGetSymbolAddress((void**)&XA,  g_XA);
    cudaGetSymbolAddress((void**)&W,   g_W);
    cudaGetSymbolAddress((void**)&Y1,  g_Y1);
    cudaGetSymbolAddress((void**)&Y2,  g_Y2);
    cudaGetSymbolAddress((void**)&XAh, g_XAh);
    cudaGetSymbolAddress((void**)&XAl, g_XAl);
    cudaGetSymbolAddress((void**)&Wh,  g_Wh);
    cudaGetSymbolAddress((void**)&Wl,  g_Wl);

    cudaFuncSetAttribute(gemm_hmma, cudaFuncAttributeMaxDynamicSharedMemorySize, DSMEM);

    // ---- layer 0 ----
    expand0_kernel<<<dim3(N_BATCH / 256, FP0), 256>>>(xs, ys, XA);
    build_w_kernel<<<dim3(E / 256, FP0), 256>>>(bw0, sw0, sc0, W, E, F0);
    conv_tiles<<<dim3(CH0, MT), 256>>>(XA, XAh, XAl, N_BATCH, CH0);
    conv_tiles<<<dim3(CH0, E / 128), 256>>>(W, Wh, Wl, E, CH0);
    gemm_hmma<<<dim3(E / 256, MT), 256, DSMEM>>>(XAh, XAl, Wh, Wl, Y1, E, CH0);

    // ---- layer 1 ----
    expand_kernel<<<dim3(N_BATCH / 256, E), 256>>>(Y1, XA, E);
    build_w_kernel<<<dim3(E / 256, E), 256>>>(bw1, sw1, sc1, W, E, E);
    conv_tiles<<<dim3(CH1, MT), 256>>>(XA, XAh, XAl, N_BATCH, CH1);
    conv_tiles<<<dim3(CH1, E / 128), 256>>>(W, Wh, Wl, E, CH1);
    gemm_hmma<<<dim3(E / 256, MT), 256, DSMEM>>>(XAh, XAl, Wh, Wl, Y2, E, CH1);

    // ---- layer 2 ----
    expand_kernel<<<dim3(N_BATCH / 256, E), 256>>>(Y2, XA, E);
    build_w_kernel<<<dim3(OUTW / 256, E), 256>>>(bw2, sw2, sc2, W, OUTW, E);
    conv_tiles<<<dim3(CH1, MT), 256>>>(XA, XAh, XAl, N_BATCH, CH1);
    conv_tiles<<<dim3(CH1, OUTW / 128), 256>>>(W, Wh, Wl, OUTW, CH1);
    gemm_hmma<<<dim3(OUTW / 256, MT), 256, DSMEM>>>(XAh, XAl, Wh, Wl, out, OUTW, CH1);
}